// round 3
// baseline (speedup 1.0000x reference)
#include <cuda_runtime.h>

#define N_USER   100000
#define N_ITEM   100000
#define N_EDGE   1600000
#define IN_DIM   128
#define OUT_DIM  64
#define NEG_SLOPE 0.01f

// ---------------- device scratch (static, no runtime alloc) ----------------
__device__ float g_Wh_user[(size_t)N_USER * OUT_DIM];   // 25.6 MB
__device__ float g_Wh_item[(size_t)N_ITEM * OUT_DIM];   // 25.6 MB
__device__ float g_su_src[N_USER];
__device__ float g_su_dst[N_USER];
__device__ float g_si_src[N_ITEM];
__device__ float g_si_dst[N_ITEM];
__device__ float g_den_user[N_USER];
__device__ float g_den_item[N_ITEM];

// ---------------- zero output + softmax denominators each replay ------------
__global__ __launch_bounds__(256) void zero_kernel(
    float4* __restrict__ out4, float* __restrict__ den_u, float* __restrict__ den_i)
{
    int i = blockIdx.x * blockDim.x + threadIdx.x;
    const int total4 = (N_USER + N_ITEM) * OUT_DIM / 4;   // 3.2M float4
    if (i < total4) out4[i] = make_float4(0.f, 0.f, 0.f, 0.f);
    if (i < N_USER) den_u[i] = 0.f;
    if (i < N_ITEM) den_i[i] = 0.f;
}

// ---------------- Wh = feat @ W + b  (16 rows / block, 256 thr) ----------------
__global__ __launch_bounds__(256) void linear_kernel(
    const float* __restrict__ feat, const float* __restrict__ W,
    const float* __restrict__ b, float* __restrict__ Wh, int n)
{
    __shared__ float Ws[IN_DIM * OUT_DIM];   // 32 KB
    __shared__ float fs[16][IN_DIM];         // 8 KB
    int tid = threadIdx.x;

    #pragma unroll
    for (int i = tid; i < IN_DIM * OUT_DIM; i += 256) Ws[i] = W[i];

    int row0 = blockIdx.x * 16;
    const float4* fsrc = reinterpret_cast<const float4*>(feat + (size_t)row0 * IN_DIM);
    float4* fdst = reinterpret_cast<float4*>(&fs[0][0]);
    #pragma unroll
    for (int i = tid; i < 16 * IN_DIM / 4; i += 256) fdst[i] = fsrc[i];
    __syncthreads();

    int j  = tid & 63;      // output column
    int rg = tid >> 6;      // row group: 4 rows per thread
    float bj = b[j];

    const float* f0 = fs[rg * 4 + 0];
    const float* f1 = fs[rg * 4 + 1];
    const float* f2 = fs[rg * 4 + 2];
    const float* f3 = fs[rg * 4 + 3];

    float acc0 = 0.f, acc1 = 0.f, acc2 = 0.f, acc3 = 0.f;
    #pragma unroll 16
    for (int k = 0; k < IN_DIM; k++) {
        float w = Ws[k * OUT_DIM + j];
        acc0 = fmaf(f0[k], w, acc0);
        acc1 = fmaf(f1[k], w, acc1);
        acc2 = fmaf(f2[k], w, acc2);
        acc3 = fmaf(f3[k], w, acc3);
    }

    int r = row0 + rg * 4;
    if (r + 3 < n) {
        Wh[(size_t)(r + 0) * OUT_DIM + j] = acc0 + bj;
        Wh[(size_t)(r + 1) * OUT_DIM + j] = acc1 + bj;
        Wh[(size_t)(r + 2) * OUT_DIM + j] = acc2 + bj;
        Wh[(size_t)(r + 3) * OUT_DIM + j] = acc3 + bj;
    } else {
        if (r + 0 < n) Wh[(size_t)(r + 0) * OUT_DIM + j] = acc0 + bj;
        if (r + 1 < n) Wh[(size_t)(r + 1) * OUT_DIM + j] = acc1 + bj;
        if (r + 2 < n) Wh[(size_t)(r + 2) * OUT_DIM + j] = acc2 + bj;
        if (r + 3 < n) Wh[(size_t)(r + 3) * OUT_DIM + j] = acc3 + bj;
    }
}

// ---------------- per-node attention scalars ----------------
__global__ __launch_bounds__(256) void attn_scalar_kernel(
    const float* __restrict__ Wh, const float* __restrict__ attn,
    float* __restrict__ s_src, float* __restrict__ s_dst, int n)
{
    int warp = (blockIdx.x * blockDim.x + threadIdx.x) >> 5;
    int lane = threadIdx.x & 31;
    if (warp >= n) return;

    float a0 = attn[lane],      a1 = attn[lane + 32];        // a_src halves
    float c0 = attn[64 + lane], c1 = attn[96 + lane];        // a_dst halves
    float v0 = Wh[(size_t)warp * OUT_DIM + lane];
    float v1 = Wh[(size_t)warp * OUT_DIM + 32 + lane];

    float ps = fmaf(v0, a0, v1 * a1);
    float pd = fmaf(v0, c0, v1 * c1);
    #pragma unroll
    for (int o = 16; o; o >>= 1) {
        ps += __shfl_xor_sync(0xffffffffu, ps, o);
        pd += __shfl_xor_sync(0xffffffffu, pd, o);
    }
    if (lane == 0) { s_src[warp] = ps; s_dst[warp] = pd; }
}

// ---------------- edge pass 1: denom[dst] += exp(lrelu(e)) ----------------
// Softmax is shift-invariant; segment_max dropped (|e| small, no overflow).
__global__ __launch_bounds__(256) void edge_pass1_kernel(
    const int* __restrict__ src, const int* __restrict__ dst,
    const float* __restrict__ ssrc, const float* __restrict__ sdst,
    float* __restrict__ denom)
{
    int e = blockIdx.x * blockDim.x + threadIdx.x;
    if (e >= N_EDGE) return;
    int d = dst[e];
    float v = ssrc[src[e]] + sdst[d];
    v = v > 0.f ? v : NEG_SLOPE * v;
    atomicAdd(&denom[d], __expf(v));
}

// ---------------- edge pass 2: out[dst] += alpha * Wh_src[src] ----------------
__global__ __launch_bounds__(256) void edge_pass2_kernel(
    const int* __restrict__ src, const int* __restrict__ dst,
    const float* __restrict__ ssrc, const float* __restrict__ sdst,
    const float* __restrict__ denom, const float* __restrict__ Whs,
    float* __restrict__ out)
{
    int t = blockIdx.x * blockDim.x + threadIdx.x;
    int e = t >> 4;
    if (e >= N_EDGE) return;
    int sub = t & 15;

    int s = src[e], d = dst[e];
    float v = ssrc[s] + sdst[d];
    v = v > 0.f ? v : NEG_SLOPE * v;
    float alpha = __expf(v) / denom[d];

    float4 z = *reinterpret_cast<const float4*>(Whs + (size_t)s * OUT_DIM + sub * 4);
    float* o = out + (size_t)d * OUT_DIM + sub * 4;
    atomicAdd(o + 0, alpha * z.x);
    atomicAdd(o + 1, alpha * z.y);
    atomicAdd(o + 2, alpha * z.z);
    atomicAdd(o + 3, alpha * z.w);
}

// ---------------- launch ----------------
extern "C" void kernel_launch(void* const* d_in, const int* in_sizes, int n_in,
                              void* d_out, int out_size)
{
    const float* feat_user = (const float*)d_in[0];
    const float* feat_item = (const float*)d_in[1];
    const float* W_user    = (const float*)d_in[2];
    const float* b_user    = (const float*)d_in[3];
    const float* W_item    = (const float*)d_in[4];
    const float* b_item    = (const float*)d_in[5];
    const float* attn_w    = (const float*)d_in[6];
    const int*   src_u2i   = (const int*)d_in[7];
    const int*   dst_u2i   = (const int*)d_in[8];
    const int*   src_i2u   = (const int*)d_in[9];
    const int*   dst_i2u   = (const int*)d_in[10];
    float* out = (float*)d_out;

    // CRITICAL: get true DEVICE addresses of __device__ globals. Passing the
    // symbol name from host code passes the host shadow address, which on
    // GB300 (ATS) silently resolves to host memory -> never-zeroed
    // accumulators + C2C-speed gathers. (Root cause of rounds 1-2.)
    float *Wh_user, *Wh_item, *su_src, *su_dst, *si_src, *si_dst, *den_user, *den_item;
    cudaGetSymbolAddress((void**)&Wh_user,  g_Wh_user);
    cudaGetSymbolAddress((void**)&Wh_item,  g_Wh_item);
    cudaGetSymbolAddress((void**)&su_src,   g_su_src);
    cudaGetSymbolAddress((void**)&su_dst,   g_su_dst);
    cudaGetSymbolAddress((void**)&si_src,   g_si_src);
    cudaGetSymbolAddress((void**)&si_dst,   g_si_dst);
    cudaGetSymbolAddress((void**)&den_user, g_den_user);
    cudaGetSymbolAddress((void**)&den_item, g_den_item);

    // zero output + denominators (kernel node, replayed every graph launch)
    const int total4 = (N_USER + N_ITEM) * OUT_DIM / 4;
    zero_kernel<<<(total4 + 255) / 256, 256>>>((float4*)out, den_user, den_item);

    // Wh = feat @ W + b
    linear_kernel<<<(N_USER + 15) / 16, 256>>>(feat_user, W_user, b_user, Wh_user, N_USER);
    linear_kernel<<<(N_ITEM + 15) / 16, 256>>>(feat_item, W_item, b_item, Wh_item, N_ITEM);

    // per-node attention scalars
    attn_scalar_kernel<<<(N_USER * 32 + 255) / 256, 256>>>(Wh_user, attn_w, su_src, su_dst, N_USER);
    attn_scalar_kernel<<<(N_ITEM * 32 + 255) / 256, 256>>>(Wh_item, attn_w, si_src, si_dst, N_ITEM);

    // u2i: src=user, dst=item -> h_item (second half of out)
    edge_pass1_kernel<<<(N_EDGE + 255) / 256, 256>>>(src_u2i, dst_u2i, su_src, si_dst, den_item);
    // i2u: src=item, dst=user -> h_user (first half of out)
    edge_pass1_kernel<<<(N_EDGE + 255) / 256, 256>>>(src_i2u, dst_i2u, si_src, su_dst, den_user);

    edge_pass2_kernel<<<(N_EDGE * 16 + 255) / 256, 256>>>(
        src_u2i, dst_u2i, su_src, si_dst, den_item, Wh_user, out + (size_t)N_USER * OUT_DIM);
    edge_pass2_kernel<<<(N_EDGE * 16 + 255) / 256, 256>>>(
        src_i2u, dst_i2u, si_src, su_dst, den_user, Wh_item, out);
}

// round 4
// speedup vs baseline: 1.6530x; 1.6530x over previous
#include <cuda_runtime.h>

#define N_USER   100000
#define N_ITEM   100000
#define N_EDGE   1600000
#define IN_DIM   128
#define OUT_DIM  64
#define NEG_SLOPE 0.01f

// ---------------- device scratch (static, no runtime alloc) ----------------
__device__ float g_Wh_user[(size_t)N_USER * OUT_DIM];   // 25.6 MB
__device__ float g_Wh_item[(size_t)N_ITEM * OUT_DIM];   // 25.6 MB
__device__ float g_su_src[N_USER];
__device__ float g_su_dst[N_USER];
__device__ float g_si_src[N_ITEM];
__device__ float g_si_dst[N_ITEM];
__device__ float g_den_user[N_USER];
__device__ float g_den_item[N_ITEM];
__device__ float g_ex_u2i[N_EDGE];   // staged exp(lrelu(e)) per edge
__device__ float g_ex_i2u[N_EDGE];

// ---------------- zero output + softmax denominators each replay ------------
__global__ __launch_bounds__(256) void zero_kernel(
    float4* __restrict__ out4, float* __restrict__ den_u, float* __restrict__ den_i)
{
    int i = blockIdx.x * blockDim.x + threadIdx.x;
    const int total4 = (N_USER + N_ITEM) * OUT_DIM / 4;   // 3.2M float4
    if (i < total4) out4[i] = make_float4(0.f, 0.f, 0.f, 0.f);
    if (i < N_USER) den_u[i] = 0.f;
    if (i < N_ITEM) den_i[i] = 0.f;
}

// ------- Wh = feat @ W + b, fused with s_src = Wh.a_src, s_dst = Wh.a_dst -------
// 16 rows / block (N = 100000 = 6250 * 16, exact), 256 threads.
__global__ __launch_bounds__(256) void linear_attn_kernel(
    const float* __restrict__ feat, const float* __restrict__ W,
    const float* __restrict__ b, const float* __restrict__ attn,
    float* __restrict__ Wh, float* __restrict__ s_src, float* __restrict__ s_dst)
{
    __shared__ float Ws[IN_DIM * OUT_DIM];   // 32 KB
    __shared__ float fs[16][IN_DIM];         // 8 KB
    __shared__ float sWh[16][OUT_DIM];       // 4 KB (Wh tile incl bias)
    int tid = threadIdx.x;

    #pragma unroll
    for (int i = tid; i < IN_DIM * OUT_DIM; i += 256) Ws[i] = W[i];

    int row0 = blockIdx.x * 16;
    const float4* fsrc = reinterpret_cast<const float4*>(feat + (size_t)row0 * IN_DIM);
    float4* fdst = reinterpret_cast<float4*>(&fs[0][0]);
    #pragma unroll
    for (int i = tid; i < 16 * IN_DIM / 4; i += 256) fdst[i] = fsrc[i];
    __syncthreads();

    int j  = tid & 63;      // output column
    int rg = tid >> 6;      // row group: 4 rows per thread
    float bj = b[j];

    const float* f0 = fs[rg * 4 + 0];
    const float* f1 = fs[rg * 4 + 1];
    const float* f2 = fs[rg * 4 + 2];
    const float* f3 = fs[rg * 4 + 3];

    float acc0 = 0.f, acc1 = 0.f, acc2 = 0.f, acc3 = 0.f;
    #pragma unroll 16
    for (int k = 0; k < IN_DIM; k++) {
        float w = Ws[k * OUT_DIM + j];
        acc0 = fmaf(f0[k], w, acc0);
        acc1 = fmaf(f1[k], w, acc1);
        acc2 = fmaf(f2[k], w, acc2);
        acc3 = fmaf(f3[k], w, acc3);
    }
    acc0 += bj; acc1 += bj; acc2 += bj; acc3 += bj;

    int r = row0 + rg * 4;
    Wh[(size_t)(r + 0) * OUT_DIM + j] = acc0;
    Wh[(size_t)(r + 1) * OUT_DIM + j] = acc1;
    Wh[(size_t)(r + 2) * OUT_DIM + j] = acc2;
    Wh[(size_t)(r + 3) * OUT_DIM + j] = acc3;

    sWh[rg * 4 + 0][j] = acc0;
    sWh[rg * 4 + 1][j] = acc1;
    sWh[rg * 4 + 2][j] = acc2;
    sWh[rg * 4 + 3][j] = acc3;
    __syncthreads();

    // scalar epilogue: 8 warps x 2 rows each
    int wid  = tid >> 5;
    int lane = tid & 31;
    float a0 = attn[lane],      a1 = attn[lane + 32];   // a_src halves
    float c0 = attn[64 + lane], c1 = attn[96 + lane];   // a_dst halves

    #pragma unroll
    for (int rr = 0; rr < 2; rr++) {
        int row = wid * 2 + rr;
        float v0 = sWh[row][lane];
        float v1 = sWh[row][lane + 32];
        float ps = fmaf(v0, a0, v1 * a1);
        float pd = fmaf(v0, c0, v1 * c1);
        #pragma unroll
        for (int o = 16; o; o >>= 1) {
            ps += __shfl_xor_sync(0xffffffffu, ps, o);
            pd += __shfl_xor_sync(0xffffffffu, pd, o);
        }
        if (lane == 0) { s_src[row0 + row] = ps; s_dst[row0 + row] = pd; }
    }
}

// ---------------- edge pass 1: ex = exp(lrelu(e)); denom[dst] += ex ----------
// Softmax is shift-invariant; segment_max dropped (|e| small, no overflow).
__global__ __launch_bounds__(256) void edge_pass1_kernel(
    const int* __restrict__ src, const int* __restrict__ dst,
    const float* __restrict__ ssrc, const float* __restrict__ sdst,
    float* __restrict__ denom, float* __restrict__ ex_out)
{
    int e = blockIdx.x * blockDim.x + threadIdx.x;
    if (e >= N_EDGE) return;
    int d = dst[e];
    float v = ssrc[src[e]] + sdst[d];
    v = v > 0.f ? v : NEG_SLOPE * v;
    float ex = __expf(v);
    ex_out[e] = ex;
    atomicAdd(&denom[d], ex);
}

// ---------------- edge pass 2: out[dst] += alpha * Wh_src[src] ----------------
// 8 lanes per edge; each lane does 2 float4 gathers + 2 vector REDs.
__global__ __launch_bounds__(256) void edge_pass2_kernel(
    const int* __restrict__ src, const int* __restrict__ dst,
    const float* __restrict__ ex, const float* __restrict__ denom,
    const float4* __restrict__ Whs4, float4* __restrict__ out4)
{
    int t = blockIdx.x * blockDim.x + threadIdx.x;
    int e = t >> 3;
    if (e >= N_EDGE) return;
    int sub = t & 7;

    int d = dst[e];
    float alpha = ex[e] / denom[d];
    int s = src[e];

    float4 z0 = Whs4[(size_t)s * 16 + sub];
    float4 z1 = Whs4[(size_t)s * 16 + sub + 8];
    float4 r0 = make_float4(alpha * z0.x, alpha * z0.y, alpha * z0.z, alpha * z0.w);
    float4 r1 = make_float4(alpha * z1.x, alpha * z1.y, alpha * z1.z, alpha * z1.w);

    float4* o0 = out4 + (size_t)d * 16 + sub;
    float4* o1 = o0 + 8;
    asm volatile("red.global.add.v4.f32 [%0], {%1,%2,%3,%4};"
                 :: "l"(o0), "f"(r0.x), "f"(r0.y), "f"(r0.z), "f"(r0.w) : "memory");
    asm volatile("red.global.add.v4.f32 [%0], {%1,%2,%3,%4};"
                 :: "l"(o1), "f"(r1.x), "f"(r1.y), "f"(r1.z), "f"(r1.w) : "memory");
}

// ---------------- launch ----------------
extern "C" void kernel_launch(void* const* d_in, const int* in_sizes, int n_in,
                              void* d_out, int out_size)
{
    const float* feat_user = (const float*)d_in[0];
    const float* feat_item = (const float*)d_in[1];
    const float* W_user    = (const float*)d_in[2];
    const float* b_user    = (const float*)d_in[3];
    const float* W_item    = (const float*)d_in[4];
    const float* b_item    = (const float*)d_in[5];
    const float* attn_w    = (const float*)d_in[6];
    const int*   src_u2i   = (const int*)d_in[7];
    const int*   dst_u2i   = (const int*)d_in[8];
    const int*   src_i2u   = (const int*)d_in[9];
    const int*   dst_i2u   = (const int*)d_in[10];
    float* out = (float*)d_out;

    // true DEVICE addresses of __device__ globals (host shadow + ATS trap!)
    float *Wh_user, *Wh_item, *su_src, *su_dst, *si_src, *si_dst,
          *den_user, *den_item, *ex_u2i, *ex_i2u;
    cudaGetSymbolAddress((void**)&Wh_user,  g_Wh_user);
    cudaGetSymbolAddress((void**)&Wh_item,  g_Wh_item);
    cudaGetSymbolAddress((void**)&su_src,   g_su_src);
    cudaGetSymbolAddress((void**)&su_dst,   g_su_dst);
    cudaGetSymbolAddress((void**)&si_src,   g_si_src);
    cudaGetSymbolAddress((void**)&si_dst,   g_si_dst);
    cudaGetSymbolAddress((void**)&den_user, g_den_user);
    cudaGetSymbolAddress((void**)&den_item, g_den_item);
    cudaGetSymbolAddress((void**)&ex_u2i,   g_ex_u2i);
    cudaGetSymbolAddress((void**)&ex_i2u,   g_ex_i2u);

    // zero output + denominators (kernel node, replayed every graph launch)
    const int total4 = (N_USER + N_ITEM) * OUT_DIM / 4;
    zero_kernel<<<(total4 + 255) / 256, 256>>>((float4*)out, den_user, den_item);

    // Wh = feat @ W + b, fused attention scalars
    linear_attn_kernel<<<N_USER / 16, 256>>>(feat_user, W_user, b_user, attn_w,
                                             Wh_user, su_src, su_dst);
    linear_attn_kernel<<<N_ITEM / 16, 256>>>(feat_item, W_item, b_item, attn_w,
                                             Wh_item, si_src, si_dst);

    // u2i: src=user, dst=item -> h_item (second half of out)
    edge_pass1_kernel<<<(N_EDGE + 255) / 256, 256>>>(src_u2i, dst_u2i, su_src, si_dst,
                                                     den_item, ex_u2i);
    // i2u: src=item, dst=user -> h_user (first half of out)
    edge_pass1_kernel<<<(N_EDGE + 255) / 256, 256>>>(src_i2u, dst_i2u, si_src, su_dst,
                                                     den_user, ex_i2u);

    edge_pass2_kernel<<<(N_EDGE * 8 + 255) / 256, 256>>>(
        src_u2i, dst_u2i, ex_u2i, den_item, (const float4*)Wh_user,
        (float4*)(out + (size_t)N_USER * OUT_DIM));
    edge_pass2_kernel<<<(N_EDGE * 8 + 255) / 256, 256>>>(
        src_i2u, dst_i2u, ex_i2u, den_user, (const float4*)Wh_item,
        (float4*)out);
}

// round 5
// speedup vs baseline: 1.9506x; 1.1800x over previous
#include <cuda_runtime.h>

#define N_USER   100000
#define N_ITEM   100000
#define N_NODE2  200000          // combined dst-node space: [0,100K)=item(u2i), [100K,200K)=user(i2u)
#define N_EDGE   1600000
#define N_EDGE2  3200000
#define IN_DIM   128
#define OUT_DIM  64
#define NEG_SLOPE 0.01f
#define LROWS    32
#define NBLK_SCAN 196            // ceil(200000/1024)

// ---------------- device scratch (static, no runtime alloc) ----------------
__device__ float g_Wh_user[(size_t)N_USER * OUT_DIM];   // 25.6 MB
__device__ float g_Wh_item[(size_t)N_ITEM * OUT_DIM];   // 25.6 MB
__device__ float g_su_src[N_USER];
__device__ float g_su_dst[N_USER];
__device__ float g_si_src[N_ITEM];
__device__ float g_si_dst[N_ITEM];
__device__ float g_den[N_NODE2];
__device__ int   g_cnt[N_NODE2];
__device__ int   g_offs[N_NODE2];
__device__ int   g_cursor[N_NODE2];
__device__ int   g_bsum[NBLK_SCAN];
__device__ int   g_boff[NBLK_SCAN];
__device__ int   g_csr_src[N_EDGE2];   // 12.8 MB
__device__ float g_csr_ex[N_EDGE2];    // 12.8 MB

// ---------------- per-replay reset: counters + denominators ----------------
__global__ __launch_bounds__(256) void zero_kernel(int* __restrict__ cnt,
                                                   float* __restrict__ den)
{
    int i = blockIdx.x * blockDim.x + threadIdx.x;
    if (i < N_NODE2) { cnt[i] = 0; den[i] = 0.f; }
}

// ------- Wh = feat @ W + b fused with s_src/s_dst epilogue -------
// 32 rows/block, 256 threads: thread = (cg in [0,32): 2 cols, rg in [0,8): 4 rows)
__global__ __launch_bounds__(256) void linear_attn_kernel(
    const float* __restrict__ feat, const float* __restrict__ W,
    const float* __restrict__ b, const float* __restrict__ attn,
    float* __restrict__ Wh, float* __restrict__ s_src, float* __restrict__ s_dst)
{
    __shared__ float Ws[IN_DIM * OUT_DIM];   // 32 KB
    __shared__ float fs[LROWS][IN_DIM];      // 16 KB (reused for Wh tile)
    int tid = threadIdx.x;

    #pragma unroll
    for (int i = tid; i < IN_DIM * OUT_DIM; i += 256) Ws[i] = W[i];

    int row0 = blockIdx.x * LROWS;
    const float4* fsrc = reinterpret_cast<const float4*>(feat + (size_t)row0 * IN_DIM);
    float4* fdst = reinterpret_cast<float4*>(&fs[0][0]);
    #pragma unroll
    for (int i = tid; i < LROWS * IN_DIM / 4; i += 256) fdst[i] = fsrc[i];
    __syncthreads();

    int cg = tid & 31;   // column pair index
    int rg = tid >> 5;   // row group (4 rows)
    const float2* Ws2 = reinterpret_cast<const float2*>(Ws);
    float2 acc[4] = {{0.f,0.f},{0.f,0.f},{0.f,0.f},{0.f,0.f}};

    #pragma unroll 8
    for (int k = 0; k < IN_DIM; k++) {
        float2 w = Ws2[k * 32 + cg];
        #pragma unroll
        for (int r = 0; r < 4; r++) {
            float f = fs[rg * 4 + r][k];
            acc[r].x = fmaf(f, w.x, acc[r].x);
            acc[r].y = fmaf(f, w.y, acc[r].y);
        }
    }

    float2 b2 = reinterpret_cast<const float2*>(b)[cg];
    __syncthreads();   // done reading fs; reuse as Wh tile
    float2* sWh2 = reinterpret_cast<float2*>(&fs[0][0]);   // [32][32] float2
    #pragma unroll
    for (int r = 0; r < 4; r++) {
        acc[r].x += b2.x; acc[r].y += b2.y;
        int row = rg * 4 + r;
        reinterpret_cast<float2*>(Wh)[(size_t)(row0 + row) * 32 + cg] = acc[r];
        sWh2[row * 32 + cg] = acc[r];
    }
    __syncthreads();

    // epilogue: 8 warps x 4 rows
    int wid = tid >> 5, lane = tid & 31;
    float a0 = attn[lane],      a1 = attn[lane + 32];
    float c0 = attn[64 + lane], c1 = attn[96 + lane];
    const float* sWh = &fs[0][0];
    #pragma unroll
    for (int rr = 0; rr < 4; rr++) {
        int row = wid * 4 + rr;
        float v0 = sWh[row * 64 + lane];
        float v1 = sWh[row * 64 + lane + 32];
        float ps = fmaf(v0, a0, v1 * a1);
        float pd = fmaf(v0, c0, v1 * c1);
        #pragma unroll
        for (int o = 16; o; o >>= 1) {
            ps += __shfl_xor_sync(0xffffffffu, ps, o);
            pd += __shfl_xor_sync(0xffffffffu, pd, o);
        }
        if (lane == 0) { s_src[row0 + row] = ps; s_dst[row0 + row] = pd; }
    }
}

// ---------------- histogram of dst degrees (4 edges/thread) ----------------
__global__ __launch_bounds__(256) void hist_kernel(const int4* __restrict__ dst4,
                                                   int* __restrict__ cnt, int gbase)
{
    int i = blockIdx.x * blockDim.x + threadIdx.x;
    if (i >= N_EDGE / 4) return;
    int4 d = dst4[i];
    atomicAdd(&cnt[gbase + d.x], 1);
    atomicAdd(&cnt[gbase + d.y], 1);
    atomicAdd(&cnt[gbase + d.z], 1);
    atomicAdd(&cnt[gbase + d.w], 1);
}

// ---------------- exclusive scan (3 kernels) ----------------
__global__ __launch_bounds__(256) void scan1_kernel(const int* __restrict__ cnt,
        int* __restrict__ offs, int* __restrict__ bsum)
{
    __shared__ int wsum[8];
    int tid = threadIdx.x;
    int base = blockIdx.x * 1024 + tid * 4;
    int v[4];
    #pragma unroll
    for (int q = 0; q < 4; q++) { int i = base + q; v[q] = (i < N_NODE2) ? cnt[i] : 0; }
    int t = v[0] + v[1] + v[2] + v[3];
    int lane = tid & 31, wid = tid >> 5;
    int inc = t;
    #pragma unroll
    for (int o = 1; o < 32; o <<= 1) { int n = __shfl_up_sync(0xffffffffu, inc, o); if (lane >= o) inc += n; }
    if (lane == 31) wsum[wid] = inc;
    __syncthreads();
    if (wid == 0) {
        int ws = (lane < 8) ? wsum[lane] : 0;
        int winc = ws;
        #pragma unroll
        for (int o = 1; o < 8; o <<= 1) { int n = __shfl_up_sync(0xffffffffu, winc, o); if (lane >= o) winc += n; }
        if (lane < 8) wsum[lane] = winc - ws;          // exclusive warp offsets
        if (lane == 7) bsum[blockIdx.x] = winc;        // block total
    }
    __syncthreads();
    int run = wsum[wid] + (inc - t);
    #pragma unroll
    for (int q = 0; q < 4; q++) { int i = base + q; if (i < N_NODE2) offs[i] = run; run += v[q]; }
}

__global__ __launch_bounds__(256) void scan2_kernel(const int* __restrict__ bsum,
                                                    int* __restrict__ boff)
{
    __shared__ int wsum[8];
    int tid = threadIdx.x;
    int v = (tid < NBLK_SCAN) ? bsum[tid] : 0;
    int lane = tid & 31, wid = tid >> 5;
    int inc = v;
    #pragma unroll
    for (int o = 1; o < 32; o <<= 1) { int n = __shfl_up_sync(0xffffffffu, inc, o); if (lane >= o) inc += n; }
    if (lane == 31) wsum[wid] = inc;
    __syncthreads();
    if (wid == 0) {
        int ws = (lane < 8) ? wsum[lane] : 0;
        int winc = ws;
        #pragma unroll
        for (int o = 1; o < 8; o <<= 1) { int n = __shfl_up_sync(0xffffffffu, winc, o); if (lane >= o) winc += n; }
        if (lane < 8) wsum[lane] = winc - ws;
    }
    __syncthreads();
    if (tid < NBLK_SCAN) boff[tid] = wsum[wid] + (inc - v);
}

__global__ __launch_bounds__(256) void scan3_kernel(int* __restrict__ offs,
        const int* __restrict__ boff, int* __restrict__ cursor)
{
    int i = blockIdx.x * blockDim.x + threadIdx.x;
    if (i >= N_NODE2) return;
    int o = offs[i] + boff[i >> 10];
    offs[i] = o;
    cursor[i] = o;
}

// --------- scatter: ex = exp(lrelu(e)); denom += ex; place (src, ex) in CSR ---------
__global__ __launch_bounds__(256) void scatter_kernel(
    const int* __restrict__ src, const int* __restrict__ dst,
    const float* __restrict__ ssrc, const float* __restrict__ sdst,
    float* __restrict__ den, int* __restrict__ cursor,
    int* __restrict__ csr_src, float* __restrict__ csr_ex, int gbase)
{
    int e = blockIdx.x * blockDim.x + threadIdx.x;
    if (e >= N_EDGE) return;
    int s = src[e], d = dst[e];
    float v = ssrc[s] + sdst[d];
    v = v > 0.f ? v : NEG_SLOPE * v;
    float ex = __expf(v);
    int gd = gbase + d;
    atomicAdd(&den[gd], ex);
    int pos = atomicAdd(&cursor[gd], 1);
    csr_src[pos] = s;
    csr_ex[pos]  = ex;
}

// --------- aggregate: warp per dst node, register accumulation, one store ---------
__global__ __launch_bounds__(256) void agg_kernel(
    const int* __restrict__ offs, const int* __restrict__ csr_src,
    const float* __restrict__ csr_ex, const float* __restrict__ den,
    const float2* __restrict__ Whu2, const float2* __restrict__ Whi2,
    float2* __restrict__ out2)
{
    int g = (blockIdx.x * 256 + threadIdx.x) >> 5;
    int lane = threadIdx.x & 31;
    if (g >= N_NODE2) return;

    int beg = offs[g];
    int end = (g == N_NODE2 - 1) ? N_EDGE2 : offs[g + 1];
    const float2* Wh2 = (g < N_ITEM) ? Whu2 : Whi2;            // item-dst <- user src
    int orow = (g < N_ITEM) ? (N_USER + g) : (g - N_ITEM);

    float2 acc = make_float2(0.f, 0.f);
    for (int k0 = beg; k0 < end; k0 += 32) {
        int k = k0 + lane;
        int s = 0; float ex = 0.f;
        if (k < end) { s = csr_src[k]; ex = csr_ex[k]; }
        int m = end - k0; if (m > 32) m = 32;
        #pragma unroll 4
        for (int j = 0; j < m; j++) {
            int   sj = __shfl_sync(0xffffffffu, s,  j);
            float ej = __shfl_sync(0xffffffffu, ex, j);
            float2 z = Wh2[(size_t)sj * 32 + lane];
            acc.x = fmaf(ej, z.x, acc.x);
            acc.y = fmaf(ej, z.y, acc.y);
        }
    }
    if (end > beg) {
        float inv = 1.f / den[g];
        acc.x *= inv; acc.y *= inv;
    }
    out2[(size_t)orow * 32 + lane] = acc;
}

// ---------------- launch ----------------
extern "C" void kernel_launch(void* const* d_in, const int* in_sizes, int n_in,
                              void* d_out, int out_size)
{
    const float* feat_user = (const float*)d_in[0];
    const float* feat_item = (const float*)d_in[1];
    const float* W_user    = (const float*)d_in[2];
    const float* b_user    = (const float*)d_in[3];
    const float* W_item    = (const float*)d_in[4];
    const float* b_item    = (const float*)d_in[5];
    const float* attn_w    = (const float*)d_in[6];
    const int*   src_u2i   = (const int*)d_in[7];
    const int*   dst_u2i   = (const int*)d_in[8];
    const int*   src_i2u   = (const int*)d_in[9];
    const int*   dst_i2u   = (const int*)d_in[10];
    float* out = (float*)d_out;

    // true DEVICE addresses of __device__ globals (host-shadow/ATS trap!)
    float *Wh_user, *Wh_item, *su_src, *su_dst, *si_src, *si_dst, *den, *csr_ex;
    int *cnt, *offs, *cursor, *bsum, *boff, *csr_src;
    cudaGetSymbolAddress((void**)&Wh_user, g_Wh_user);
    cudaGetSymbolAddress((void**)&Wh_item, g_Wh_item);
    cudaGetSymbolAddress((void**)&su_src,  g_su_src);
    cudaGetSymbolAddress((void**)&su_dst,  g_su_dst);
    cudaGetSymbolAddress((void**)&si_src,  g_si_src);
    cudaGetSymbolAddress((void**)&si_dst,  g_si_dst);
    cudaGetSymbolAddress((void**)&den,     g_den);
    cudaGetSymbolAddress((void**)&cnt,     g_cnt);
    cudaGetSymbolAddress((void**)&offs,    g_offs);
    cudaGetSymbolAddress((void**)&cursor,  g_cursor);
    cudaGetSymbolAddress((void**)&bsum,    g_bsum);
    cudaGetSymbolAddress((void**)&boff,    g_boff);
    cudaGetSymbolAddress((void**)&csr_src, g_csr_src);
    cudaGetSymbolAddress((void**)&csr_ex,  g_csr_ex);

    zero_kernel<<<(N_NODE2 + 255) / 256, 256>>>(cnt, den);

    linear_attn_kernel<<<N_USER / LROWS, 256>>>(feat_user, W_user, b_user, attn_w,
                                                Wh_user, su_src, su_dst);
    linear_attn_kernel<<<N_ITEM / LROWS, 256>>>(feat_item, W_item, b_item, attn_w,
                                                Wh_item, si_src, si_dst);

    // degree histogram (combined node space)
    hist_kernel<<<(N_EDGE / 4 + 255) / 256, 256>>>((const int4*)dst_u2i, cnt, 0);
    hist_kernel<<<(N_EDGE / 4 + 255) / 256, 256>>>((const int4*)dst_i2u, cnt, N_ITEM);

    // exclusive scan -> CSR offsets (+ cursor copy)
    scan1_kernel<<<NBLK_SCAN, 256>>>(cnt, offs, bsum);
    scan2_kernel<<<1, 256>>>(bsum, boff);
    scan3_kernel<<<(N_NODE2 + 255) / 256, 256>>>(offs, boff, cursor);

    // scatter edges into CSR, computing ex + denominators on the way
    scatter_kernel<<<(N_EDGE + 255) / 256, 256>>>(src_u2i, dst_u2i, su_src, si_dst,
                                                  den, cursor, csr_src, csr_ex, 0);
    scatter_kernel<<<(N_EDGE + 255) / 256, 256>>>(src_i2u, dst_i2u, si_src, su_dst,
                                                  den, cursor, csr_src, csr_ex, N_ITEM);

    // gather-aggregate, one coalesced store per output row (no atomics, no out-zeroing)
    agg_kernel<<<(N_NODE2 * 32 + 255) / 256, 256>>>(offs, csr_src, csr_ex, den,
                                                    (const float2*)Wh_user,
                                                    (const float2*)Wh_item,
                                                    (float2*)out);
}